// round 2
// baseline (speedup 1.0000x reference)
#include <cuda_runtime.h>

// ---------------- problem constants ----------------
#define BSZ   256           // bs = batch_size * clips_num
#define DIM   128           // feature dim
#define QK    131072        // queue size
#define NC    131073        // 1 + QK (out row length)
#define OUT_ELEMS (BSZ * (long long)NC)     // 33,554,688
#define PROBS_OFF OUT_ELEMS                  // 33,554,688
#define MEM_OFF   (OUT_ELEMS + 1)            // 33,554,689 (odd -> no vector stores)
#define T_INV 14.2857142857142857f           // 1/0.07
#define OUTPUT_SIZE 1000000.0f

// ---------------- device scratch (no allocations allowed) ----------------
__device__ float g_rowsum[BSZ];
__device__ float g_invZ;

// ---------------- f32x2 helpers (packed fp32, 2x FFMA throughput) -------
__device__ __forceinline__ unsigned long long dup2(float x) {
    unsigned long long r; unsigned int u = __float_as_uint(x);
    asm("mov.b64 %0, {%1, %1};" : "=l"(r) : "r"(u));
    return r;
}
__device__ __forceinline__ unsigned long long fma2(unsigned long long a,
                                                   unsigned long long b,
                                                   unsigned long long c) {
    unsigned long long d;
    asm("fma.rn.f32x2 %0, %1, %2, %3;" : "=l"(d) : "l"(a), "l"(b), "l"(c));
    return d;
}

// ---------------- K0: zero accumulators ----------------
__global__ void zero_k() {
    if (threadIdx.x < BSZ) g_rowsum[threadIdx.x] = 0.f;
}

// ---------------- K1: l_pos column (col 0 of out, unscaled exp) ---------
__global__ void lpos_k(const float* __restrict__ q, const float* __restrict__ k,
                       float* __restrict__ out) {
    int b = threadIdx.x;           // 256 threads, one row each
    int vid = b & 63;
    const float* qb = q + b * DIM;
    float s = 0.f;
    #pragma unroll
    for (int c = 0; c < 4; c++) {
        int r = vid + c * 64;
        if (r == b) continue;
        const float* kr = k + r * DIM;
        float d = 0.f;
        #pragma unroll
        for (int j = 0; j < DIM; j++) d += kr[j] * qb[j];
        s += d;
    }
    s *= (1.0f / 3.0f);
    float e = __expf(s * T_INV);
    out[(long long)b * NC] = e;
    atomicAdd(&g_rowsum[b], e);
}

// ---------------- K2: main GEMM + exp + row sums ----------------
// Tile: BM=128 (q rows) x BN=128 (mem rows), full K=128 resident in smem.
// 256 threads, each computes 8x8 outputs via packed f32x2 FMAs.
extern __shared__ float smem_dyn[];
__global__ __launch_bounds__(256, 1)
void gemm_k(const float* __restrict__ q, const float* __restrict__ mem,
            float* __restrict__ out) {
    float* As = smem_dyn;              // [k][m]  128x128
    float* Bs = smem_dyn + 128 * 128;  // [k][n]  128x128
    __shared__ float rowAcc[128];

    int t  = threadIdx.x;
    int bn = blockIdx.x;               // 0..1023 (N tiles)
    int bm = blockIdx.y;               // 0..1    (M tiles)

    // Stage A (q rows bm*128..), transposed to k-major
    #pragma unroll
    for (int it = 0; it < 16; it++) {
        int fid = it * 256 + t;        // over 128 rows x 32 float4
        int m  = fid >> 5;
        int k4 = fid & 31;
        float4 v = reinterpret_cast<const float4*>(q)[(bm * 128 + m) * 32 + k4];
        int kk = k4 * 4;
        As[(kk + 0) * 128 + m] = v.x; As[(kk + 1) * 128 + m] = v.y;
        As[(kk + 2) * 128 + m] = v.z; As[(kk + 3) * 128 + m] = v.w;
    }
    // Stage B (mem rows bn*128..), transposed to k-major
    #pragma unroll
    for (int it = 0; it < 16; it++) {
        int fid = it * 256 + t;
        int n  = fid >> 5;
        int k4 = fid & 31;
        float4 v = reinterpret_cast<const float4*>(mem)[((long long)bn * 128 + n) * 32 + k4];
        int kk = k4 * 4;
        Bs[(kk + 0) * 128 + n] = v.x; Bs[(kk + 1) * 128 + n] = v.y;
        Bs[(kk + 2) * 128 + n] = v.z; Bs[(kk + 3) * 128 + n] = v.w;
    }
    if (t < 128) rowAcc[t] = 0.f;
    __syncthreads();

    int tx = t & 15, ty = t >> 4;      // 16x16 thread tile
    const float4*     As4 = reinterpret_cast<const float4*>(As);      // 32 f4 / k-row
    const ulonglong2* Bs2 = reinterpret_cast<const ulonglong2*>(Bs);  // 32 u2 / k-row

    unsigned long long acc[8][4];
    #pragma unroll
    for (int i = 0; i < 8; i++)
        #pragma unroll
        for (int j = 0; j < 4; j++) acc[i][j] = 0ull;

    #pragma unroll 4
    for (int kk = 0; kk < 128; kk++) {
        float4 a0 = As4[kk * 32 + ty * 2];
        float4 a1 = As4[kk * 32 + ty * 2 + 1];
        ulonglong2 b0 = Bs2[kk * 32 + tx * 2];        // FIX: row stride is 32 u2
        ulonglong2 b1 = Bs2[kk * 32 + tx * 2 + 1];
        float a[8] = {a0.x, a0.y, a0.z, a0.w, a1.x, a1.y, a1.z, a1.w};
        unsigned long long bb[4] = {b0.x, b0.y, b1.x, b1.y};
        #pragma unroll
        for (int i = 0; i < 8; i++) {
            unsigned long long ad = dup2(a[i]);
            #pragma unroll
            for (int j = 0; j < 4; j++) acc[i][j] = fma2(ad, bb[j], acc[i][j]);
        }
    }

    // Epilogue: exp, store (unscaled), per-row sums
    int m0 = bm * 128 + ty * 8;
    long long nbase = (long long)bn * 128 + tx * 8;
    #pragma unroll
    for (int i = 0; i < 8; i++) {
        float rs = 0.f;
        long long rowoff = (long long)(m0 + i) * NC + 1 + nbase;
        #pragma unroll
        for (int j = 0; j < 4; j++) {
            float2 f = *reinterpret_cast<float2*>(&acc[i][j]);
            float e0 = __expf(f.x * T_INV);
            float e1 = __expf(f.y * T_INV);
            out[rowoff + 2 * j]     = e0;
            out[rowoff + 2 * j + 1] = e1;
            rs += e0 + e1;
        }
        atomicAdd(&rowAcc[ty * 8 + i], rs);
    }
    __syncthreads();
    if (t < 128) atomicAdd(&g_rowsum[bm * 128 + t], rowAcc[t]);
}

// ---------------- K3: finalize Z, invZ, probs ----------------
__global__ void finalize_k(float* __restrict__ out) {
    __shared__ float sZ[256], sP[256];
    int t = threadIdx.x;
    float rs = g_rowsum[t];
    float e0 = out[(long long)t * NC];   // unscaled l_pos exp
    sZ[t] = rs;
    sP[t] = e0 / rs;                     // Z cancels in probs
    __syncthreads();
    for (int s = 128; s > 0; s >>= 1) {
        if (t < s) { sZ[t] += sZ[t + s]; sP[t] += sP[t + s]; }
        __syncthreads();
    }
    if (t == 0) {
        float Z = sZ[0] / ((float)BSZ * (float)NC) * OUTPUT_SIZE;
        g_invZ = 1.f / Z;
        out[PROBS_OFF] = sP[0] * (1.0f / 256.0f);
    }
}

// ---------------- K4: scale out by 1/Z ----------------
__global__ void scale_k(float* __restrict__ out) {
    float inv = g_invZ;
    long long i = (long long)blockIdx.x * blockDim.x + threadIdx.x;
    long long stride = (long long)gridDim.x * blockDim.x;
    float4* o4 = reinterpret_cast<float4*>(out);
    const long long n4 = OUT_ELEMS / 4;   // 8,388,672
    for (long long p = i; p < n4; p += stride) {
        float4 v = o4[p];
        v.x *= inv; v.y *= inv; v.z *= inv; v.w *= inv;
        o4[p] = v;
    }
}

// ---------------- K5: memory-bank update ----------------
__global__ void memup_k(const float* __restrict__ kk, const float* __restrict__ mem,
                        float* __restrict__ outm) {
    long long i = (long long)blockIdx.x * blockDim.x + threadIdx.x;
    long long stride = (long long)gridDim.x * blockDim.x;
    const long long N = (long long)QK * DIM;
    for (long long p = i; p < N; p += stride) {
        int r = (int)(p >> 7);
        int d = (int)(p & 127);
        float v;
        if (r < 64) {
            v = 0.25f * (kk[r * DIM + d] + kk[(r + 64) * DIM + d] +
                         kk[(r + 128) * DIM + d] + kk[(r + 192) * DIM + d]);
        } else {
            v = mem[p];
        }
        outm[p] = v;
    }
}

// ---------------- launch ----------------
extern "C" void kernel_launch(void* const* d_in, const int* in_sizes, int n_in,
                              void* d_out, int out_size) {
    const float* q   = (const float*)d_in[0];
    const float* k   = (const float*)d_in[1];
    const float* mem = (const float*)d_in[2];
    // d_in[3] = i (unused by the reference math)
    float* out = (float*)d_out;

    size_t smemBytes = 2 * 128 * 128 * sizeof(float);   // 128 KB
    cudaFuncSetAttribute(gemm_k, cudaFuncAttributeMaxDynamicSharedMemorySize,
                         (int)smemBytes);

    zero_k<<<1, 256>>>();
    lpos_k<<<1, 256>>>(q, k, out);
    dim3 grid(QK / 128, 2);
    gemm_k<<<grid, 256, smemBytes>>>(q, mem, out);
    finalize_k<<<1, 256>>>(out);
    scale_k<<<2048, 256>>>(out);
    memup_k<<<4096, 256>>>(k, mem, out + MEM_OFF);
}

// round 4
// speedup vs baseline: 1.9758x; 1.9758x over previous
#include <cuda_runtime.h>
#include <cuda_bf16.h>
#include <cstdint>

// ---------------- problem constants ----------------
#define BSZ   256
#define DIM   128
#define QK    131072
#define NC    131073
#define OUT_ELEMS (BSZ * (long long)NC)      // 33,554,688
#define PROBS_OFF OUT_ELEMS
#define MEM_OFF   (OUT_ELEMS + 1)
#define T_INV 14.2857142857142857f
#define OUTPUT_SIZE 1000000.0f

// ---------------- device scratch ----------------
__device__ float g_rowsum[BSZ];
__device__ float g_invZ;
__device__ __nv_bfloat16 g_mem_hi[QK * DIM];   // 32 MB
__device__ __nv_bfloat16 g_mem_lo[QK * DIM];   // 32 MB
__device__ __nv_bfloat16 g_q_hi[BSZ * DIM];
__device__ __nv_bfloat16 g_q_lo[BSZ * DIM];

// ---------------- helpers ----------------
__device__ __forceinline__ uint32_t smem_u32(const void* p) {
    uint32_t a;
    asm("{ .reg .u64 t; cvta.to.shared.u64 t, %1; cvt.u32.u64 %0, t; }" : "=r"(a) : "l"(p));
    return a;
}
__device__ __forceinline__ void ldm_x4(uint32_t* r, uint32_t addr) {
    asm volatile("ldmatrix.sync.aligned.m8n8.x4.shared.b16 {%0,%1,%2,%3}, [%4];"
                 : "=r"(r[0]), "=r"(r[1]), "=r"(r[2]), "=r"(r[3]) : "r"(addr));
}
__device__ __forceinline__ void mma_bf16(float* d, const uint32_t* a, uint32_t b0, uint32_t b1) {
    asm volatile(
        "mma.sync.aligned.m16n8k16.row.col.f32.bf16.bf16.f32 "
        "{%0,%1,%2,%3}, {%4,%5,%6,%7}, {%8,%9}, {%0,%1,%2,%3};"
        : "+f"(d[0]), "+f"(d[1]), "+f"(d[2]), "+f"(d[3])
        : "r"(a[0]), "r"(a[1]), "r"(a[2]), "r"(a[3]), "r"(b0), "r"(b1));
}

// ---------------- K-1: fp32 -> (hi, lo) bf16 split ----------------
__device__ __forceinline__ void split1(float x, __nv_bfloat16& h, __nv_bfloat16& l) {
    h = __float2bfloat16(x);
    l = __float2bfloat16(x - __bfloat162float(h));
}
__global__ void split_k(const float* __restrict__ q, const float* __restrict__ mem) {
    const long long QN4 = (BSZ * DIM) / 4;
    const long long MN4 = ((long long)QK * DIM) / 4;
    long long i = (long long)blockIdx.x * blockDim.x + threadIdx.x;
    long long stride = (long long)gridDim.x * blockDim.x;
    for (long long p = i; p < QN4 + MN4; p += stride) {
        float4 v;
        uint2* dh; uint2* dl; long long idx;
        if (p < QN4) {
            v = reinterpret_cast<const float4*>(q)[p];
            dh = reinterpret_cast<uint2*>(g_q_hi); dl = reinterpret_cast<uint2*>(g_q_lo);
            idx = p;
        } else {
            v = reinterpret_cast<const float4*>(mem)[p - QN4];
            dh = reinterpret_cast<uint2*>(g_mem_hi); dl = reinterpret_cast<uint2*>(g_mem_lo);
            idx = p - QN4;
        }
        __nv_bfloat16 h0, l0, h1, l1, h2, l2, h3, l3;
        split1(v.x, h0, l0); split1(v.y, h1, l1);
        split1(v.z, h2, l2); split1(v.w, h3, l3);
        __nv_bfloat162 hp0(h0, h1), hp1(h2, h3), lp0(l0, l1), lp1(l2, l3);
        uint2 uh, ul;
        uh.x = *reinterpret_cast<uint32_t*>(&hp0); uh.y = *reinterpret_cast<uint32_t*>(&hp1);
        ul.x = *reinterpret_cast<uint32_t*>(&lp0); ul.y = *reinterpret_cast<uint32_t*>(&lp1);
        dh[idx] = uh; dl[idx] = ul;
    }
}

// ---------------- K0 ----------------
__global__ void zero_k() {
    if (threadIdx.x < BSZ) g_rowsum[threadIdx.x] = 0.f;
}

// ---------------- K1: l_pos (fp32 exact) ----------------
__global__ void lpos_k(const float* __restrict__ q, const float* __restrict__ k,
                       float* __restrict__ out) {
    int b = threadIdx.x;
    int vid = b & 63;
    const float* qb = q + b * DIM;
    float s = 0.f;
    #pragma unroll
    for (int c = 0; c < 4; c++) {
        int r = vid + c * 64;
        if (r == b) continue;
        const float* kr = k + r * DIM;
        float d = 0.f;
        #pragma unroll
        for (int j = 0; j < DIM; j++) d += kr[j] * qb[j];
        s += d;
    }
    s *= (1.0f / 3.0f);
    float e = __expf(s * T_INV);
    out[(long long)b * NC] = e;
    atomicAdd(&g_rowsum[b], e);
}

// ---------------- K2: mma.sync split-bf16 GEMM + exp + rowsum ----------------
// SMEM 128KB: [A_hi][A_lo][B_hi][B_lo], each 128 rows x 256B (128 bf16),
// 16B chunks XOR-swizzled by (row&7) for conflict-free ldmatrix.
extern __shared__ char smem_g[];
__global__ __launch_bounds__(256, 1)
void gemm_k(float* __restrict__ out) {
    __shared__ float rowAcc[128];
    uint32_t sbase = smem_u32(smem_g);

    int t = threadIdx.x;
    int bn = blockIdx.x;       // 0..1023
    int bm = blockIdx.y;       // 0..1

    // ---- stage 4 x 32KB tiles with chunk swizzle ----
    const uint4* srcs[4] = {
        reinterpret_cast<const uint4*>(g_q_hi)   + (size_t)bm * 128 * 16,
        reinterpret_cast<const uint4*>(g_q_lo)   + (size_t)bm * 128 * 16,
        reinterpret_cast<const uint4*>(g_mem_hi) + (size_t)bn * 128 * 16,
        reinterpret_cast<const uint4*>(g_mem_lo) + (size_t)bn * 128 * 16
    };
    #pragma unroll
    for (int it = 0; it < 32; it++) {
        int fid = it * 256 + t;
        int arr = fid >> 11;
        int within = fid & 2047;
        int row = within >> 4;
        int ch  = within & 15;
        uint4 v = srcs[arr][row * 16 + ch];
        uint32_t off = (uint32_t)(arr * 32768 + row * 256 + ((ch ^ (row & 7)) << 4));
        *reinterpret_cast<uint4*>(smem_g + off) = v;
    }
    if (t < 128) rowAcc[t] = 0.f;
    __syncthreads();

    const uint32_t AH = sbase, AL = sbase + 32768, BH = sbase + 65536, BL = sbase + 98304;

    int w = t >> 5, lane = t & 31;
    int wm = w >> 1;           // 0..3 -> rows wm*32
    int wn = w & 1;            // 0..1 -> cols wn*64

    // ldmatrix thread-address components
    int a_r = (lane & 7) + ((lane >> 3) & 1) * 8;    // row within 16
    int a_c = (lane >> 4) & 1;                       // k-chunk sel
    int b_r = (lane & 7) + ((lane >> 4) & 1) * 8;    // n within 16
    int b_c = (lane >> 3) & 1;                       // k-chunk sel

    float acc[2][8][4];
    #pragma unroll
    for (int mt = 0; mt < 2; mt++)
        #pragma unroll
        for (int nt = 0; nt < 8; nt++)
            #pragma unroll
            for (int r = 0; r < 4; r++) acc[mt][nt][r] = 0.f;

    #pragma unroll
    for (int ks = 0; ks < 8; ks++) {
        uint32_t ah[2][4], al[2][4];
        #pragma unroll
        for (int mt = 0; mt < 2; mt++) {
            int r = wm * 32 + mt * 16 + a_r;
            int ch = ks * 2 + a_c;
            uint32_t off = (uint32_t)(r * 256 + ((ch ^ (r & 7)) << 4));
            ldm_x4(ah[mt], AH + off);
            ldm_x4(al[mt], AL + off);
        }
        #pragma unroll
        for (int np = 0; np < 4; np++) {
            int n = wn * 64 + np * 16 + b_r;
            int ch = ks * 2 + b_c;
            uint32_t off = (uint32_t)(n * 256 + ((ch ^ (n & 7)) << 4));
            uint32_t bh[4], bl[4];
            ldm_x4(bh, BH + off);
            ldm_x4(bl, BL + off);
            #pragma unroll
            for (int sub = 0; sub < 2; sub++) {
                int nt = np * 2 + sub;
                #pragma unroll
                for (int mt = 0; mt < 2; mt++) {
                    mma_bf16(acc[mt][nt], ah[mt], bh[2 * sub], bh[2 * sub + 1]);
                    mma_bf16(acc[mt][nt], ah[mt], bl[2 * sub], bl[2 * sub + 1]);
                    mma_bf16(acc[mt][nt], al[mt], bh[2 * sub], bh[2 * sub + 1]);
                }
            }
        }
    }

    // ---- epilogue: exp, store, rowsum ----
    int grp = lane >> 2, tid4 = lane & 3;
    #pragma unroll
    for (int mt = 0; mt < 2; mt++) {
        int r0 = wm * 32 + mt * 16 + grp;      // local row (0..127)
        int r1 = r0 + 8;
        long long m0 = (long long)(bm * 128 + r0);
        long long m1 = (long long)(bm * 128 + r1);
        long long base0 = m0 * NC + 1 + (long long)bn * 128 + wn * 64;
        long long base1 = m1 * NC + 1 + (long long)bn * 128 + wn * 64;
        float s0 = 0.f, s1 = 0.f;
        #pragma unroll
        for (int nt = 0; nt < 8; nt++) {
            int cb = nt * 8 + tid4 * 2;
            float e00 = __expf(acc[mt][nt][0] * T_INV);
            float e01 = __expf(acc[mt][nt][1] * T_INV);
            float e10 = __expf(acc[mt][nt][2] * T_INV);
            float e11 = __expf(acc[mt][nt][3] * T_INV);
            out[base0 + cb]     = e00;
            out[base0 + cb + 1] = e01;
            out[base1 + cb]     = e10;
            out[base1 + cb + 1] = e11;
            s0 += e00 + e01;
            s1 += e10 + e11;
        }
        atomicAdd(&rowAcc[r0], s0);
        atomicAdd(&rowAcc[r1], s1);
    }
    __syncthreads();
    if (t < 128) atomicAdd(&g_rowsum[bm * 128 + t], rowAcc[t]);
}

// ---------------- K3: finalize Z, invZ, probs ----------------
__global__ void finalize_k(float* __restrict__ out) {
    __shared__ float sZ[256], sP[256];
    int t = threadIdx.x;
    float rs = g_rowsum[t];
    float e0 = out[(long long)t * NC];
    sZ[t] = rs;
    sP[t] = e0 / rs;
    __syncthreads();
    for (int s = 128; s > 0; s >>= 1) {
        if (t < s) { sZ[t] += sZ[t + s]; sP[t] += sP[t + s]; }
        __syncthreads();
    }
    if (t == 0) {
        float Z = sZ[0] / ((float)BSZ * (float)NC) * OUTPUT_SIZE;
        g_invZ = 1.f / Z;
        out[PROBS_OFF] = sP[0] * (1.0f / 256.0f);
    }
}

// ---------------- K4: scale out by 1/Z ----------------
__global__ void scale_k(float* __restrict__ out) {
    float inv = g_invZ;
    long long i = (long long)blockIdx.x * blockDim.x + threadIdx.x;
    long long stride = (long long)gridDim.x * blockDim.x;
    float4* o4 = reinterpret_cast<float4*>(out);
    const long long n4 = OUT_ELEMS / 4;
    for (long long p = i; p < n4; p += stride) {
        float4 v = o4[p];
        v.x *= inv; v.y *= inv; v.z *= inv; v.w *= inv;
        o4[p] = v;
    }
}

// ---------------- K5: memory-bank update ----------------
__global__ void memup_k(const float* __restrict__ kk, const float* __restrict__ mem,
                        float* __restrict__ outm) {
    long long i = (long long)blockIdx.x * blockDim.x + threadIdx.x;
    long long stride = (long long)gridDim.x * blockDim.x;
    const long long N = (long long)QK * DIM;
    for (long long p = i; p < N; p += stride) {
        int r = (int)(p >> 7);
        int d = (int)(p & 127);
        float v;
        if (r < 64) {
            v = 0.25f * (kk[r * DIM + d] + kk[(r + 64) * DIM + d] +
                         kk[(r + 128) * DIM + d] + kk[(r + 192) * DIM + d]);
        } else {
            v = mem[p];
        }
        outm[p] = v;
    }
}

// ---------------- launch ----------------
extern "C" void kernel_launch(void* const* d_in, const int* in_sizes, int n_in,
                              void* d_out, int out_size) {
    const float* q   = (const float*)d_in[0];
    const float* k   = (const float*)d_in[1];
    const float* mem = (const float*)d_in[2];
    float* out = (float*)d_out;

    cudaFuncSetAttribute(gemm_k, cudaFuncAttributeMaxDynamicSharedMemorySize, 131072);

    split_k<<<2048, 256>>>(q, mem);
    zero_k<<<1, 256>>>();
    lpos_k<<<1, 256>>>(q, k, out);
    dim3 grid(QK / 128, 2);
    gemm_k<<<grid, 256, 131072>>>(out);
    finalize_k<<<1, 256>>>(out);
    scale_k<<<2048, 256>>>(out);
    memup_k<<<4096, 256>>>(k, mem, out + MEM_OFF);
}

// round 6
// speedup vs baseline: 2.0618x; 1.0436x over previous
#include <cuda_runtime.h>
#include <cuda_bf16.h>
#include <cstdint>

// ---------------- problem constants ----------------
#define BSZ   256
#define DIM   128
#define QK    131072
#define NC    131073
#define OUT_ELEMS (BSZ * (long long)NC)      // 33,554,688
#define PROBS_OFF OUT_ELEMS
#define MEM_OFF   (OUT_ELEMS + 1)
#define T_INV 14.2857142857142857f
#define OUTPUT_SIZE 1000000.0f
#define GRID_GEMM 148
#define NTILES    2048

// ---------------- device scratch ----------------
__device__ float g_rowsum[BSZ];
__device__ float g_invZ;
__device__ __nv_bfloat16 g_mem_hi[QK * DIM];   // 32 MB
__device__ __nv_bfloat16 g_mem_lo[QK * DIM];   // 32 MB
__device__ __nv_bfloat16 g_q_hi[BSZ * DIM];
__device__ __nv_bfloat16 g_q_lo[BSZ * DIM];

// ---------------- helpers ----------------
__device__ __forceinline__ uint32_t smem_u32(const void* p) {
    uint32_t a;
    asm("{ .reg .u64 t; cvta.to.shared.u64 t, %1; cvt.u32.u64 %0, t; }" : "=r"(a) : "l"(p));
    return a;
}
__device__ __forceinline__ void ldm_x4(uint32_t* r, uint32_t addr) {
    asm volatile("ldmatrix.sync.aligned.m8n8.x4.shared.b16 {%0,%1,%2,%3}, [%4];"
                 : "=r"(r[0]), "=r"(r[1]), "=r"(r[2]), "=r"(r[3]) : "r"(addr));
}
__device__ __forceinline__ void mma_bf16(float* d, const uint32_t* a, uint32_t b0, uint32_t b1) {
    asm volatile(
        "mma.sync.aligned.m16n8k16.row.col.f32.bf16.bf16.f32 "
        "{%0,%1,%2,%3}, {%4,%5,%6,%7}, {%8,%9}, {%0,%1,%2,%3};"
        : "+f"(d[0]), "+f"(d[1]), "+f"(d[2]), "+f"(d[3])
        : "r"(a[0]), "r"(a[1]), "r"(a[2]), "r"(a[3]), "r"(b0), "r"(b1));
}
#define CP_ASYNC16(dst, src) \
    asm volatile("{ .reg .u64 g; cvta.to.global.u64 g, %1; cp.async.cg.shared.global [%0], [g], 16; }" \
                 :: "r"(dst), "l"(src) : "memory")
#define CP_COMMIT() asm volatile("cp.async.commit_group;" ::: "memory")
#define CP_WAIT1()  asm volatile("cp.async.wait_group 1;" ::: "memory")
#define CP_WAIT0()  asm volatile("cp.async.wait_group 0;" ::: "memory")

// ---- packed f32x2 ----
__device__ __forceinline__ unsigned long long dup2(float x) {
    unsigned long long r; unsigned int u = __float_as_uint(x);
    asm("mov.b64 %0, {%1, %1};" : "=l"(r) : "r"(u));
    return r;
}
__device__ __forceinline__ unsigned long long fma2(unsigned long long a,
                                                   unsigned long long b,
                                                   unsigned long long c) {
    unsigned long long d;
    asm("fma.rn.f32x2 %0, %1, %2, %3;" : "=l"(d) : "l"(a), "l"(b), "l"(c));
    return d;
}
__device__ __forceinline__ unsigned long long add2(unsigned long long a, unsigned long long b) {
    unsigned long long d;
    asm("add.rn.f32x2 %0, %1, %2;" : "=l"(d) : "l"(a), "l"(b));
    return d;
}
__device__ __forceinline__ unsigned long long mul2(unsigned long long a, unsigned long long b) {
    unsigned long long d;
    asm("mul.rn.f32x2 %0, %1, %2;" : "=l"(d) : "l"(a), "l"(b));
    return d;
}

// exp(s/T) for a pair, via packed exp2: 2^(s*20.60993) with magic rounding + deg-5 Taylor.
__device__ __forceinline__ float2 exp_pair(float a, float b) {
    unsigned long long sp;
    asm("mov.b64 %0, {%1,%2};" : "=l"(sp) : "f"(a), "f"(b));
    const unsigned long long S  = dup2(20.60992908f);       // (1/0.07)*log2(e)
    const unsigned long long MG = dup2(12582912.0f);        // 1.5*2^23
    unsigned long long t  = fma2(sp, S, MG);
    unsigned long long nf = add2(t, dup2(-12582912.0f));    // n as float
    unsigned long long f  = fma2(sp, S, nf ^ 0x8000000080000000ULL);  // y - n
    unsigned long long r  = fma2(f, dup2(0.00133335581464f), dup2(0.00961812910763f));
    r = fma2(r, f, dup2(0.0555041086648f));
    r = fma2(r, f, dup2(0.240226506959f));
    r = fma2(r, f, dup2(0.69314718056f));
    r = fma2(r, f, dup2(1.0f));
    uint32_t t0, t1;
    asm("mov.b64 {%0,%1}, %2;" : "=r"(t0), "=r"(t1) : "l"(t));
    uint32_t sb0 = (t0 << 23) + 0x3F800000u;                // 2^n bits
    uint32_t sb1 = (t1 << 23) + 0x3F800000u;
    unsigned long long sc;
    asm("mov.b64 %0, {%1,%2};" : "=l"(sc) : "r"(sb0), "r"(sb1));
    unsigned long long res = mul2(r, sc);
    float x, y;
    asm("mov.b64 {%0,%1}, %2;" : "=f"(x), "=f"(y) : "l"(res));
    return make_float2(x, y);
}

// ---------------- K-1: fp32 -> (hi, lo) bf16 split ----------------
__device__ __forceinline__ void split1(float x, __nv_bfloat16& h, __nv_bfloat16& l) {
    h = __float2bfloat16(x);
    l = __float2bfloat16(x - __bfloat162float(h));
}
__global__ void split_k(const float* __restrict__ q, const float* __restrict__ mem) {
    const long long QN4 = (BSZ * DIM) / 4;
    const long long MN4 = ((long long)QK * DIM) / 4;
    long long i = (long long)blockIdx.x * blockDim.x + threadIdx.x;
    long long stride = (long long)gridDim.x * blockDim.x;
    for (long long p = i; p < QN4 + MN4; p += stride) {
        float4 v;
        uint2* dh; uint2* dl; long long idx;
        if (p < QN4) {
            v = reinterpret_cast<const float4*>(q)[p];
            dh = reinterpret_cast<uint2*>(g_q_hi); dl = reinterpret_cast<uint2*>(g_q_lo);
            idx = p;
        } else {
            v = reinterpret_cast<const float4*>(mem)[p - QN4];
            dh = reinterpret_cast<uint2*>(g_mem_hi); dl = reinterpret_cast<uint2*>(g_mem_lo);
            idx = p - QN4;
        }
        __nv_bfloat16 h0, l0, h1, l1, h2, l2, h3, l3;
        split1(v.x, h0, l0); split1(v.y, h1, l1);
        split1(v.z, h2, l2); split1(v.w, h3, l3);
        __nv_bfloat162 hp0(h0, h1), hp1(h2, h3), lp0(l0, l1), lp1(l2, l3);
        uint2 uh, ul;
        uh.x = *reinterpret_cast<uint32_t*>(&hp0); uh.y = *reinterpret_cast<uint32_t*>(&hp1);
        ul.x = *reinterpret_cast<uint32_t*>(&lp0); ul.y = *reinterpret_cast<uint32_t*>(&lp1);
        dh[idx] = uh; dl[idx] = ul;
    }
}

// ---------------- K0 ----------------
__global__ void zero_k() {
    if (threadIdx.x < BSZ) g_rowsum[threadIdx.x] = 0.f;
}

// ---------------- K1: l_pos (fp32 exact) ----------------
__global__ void lpos_k(const float* __restrict__ q, const float* __restrict__ k,
                       float* __restrict__ out) {
    int b = threadIdx.x;
    int vid = b & 63;
    const float* qb = q + b * DIM;
    float s = 0.f;
    #pragma unroll
    for (int c = 0; c < 4; c++) {
        int r = vid + c * 64;
        if (r == b) continue;
        const float* kr = k + r * DIM;
        float d = 0.f;
        #pragma unroll
        for (int j = 0; j < DIM; j++) d += kr[j] * qb[j];
        s += d;
    }
    s *= (1.0f / 3.0f);
    float e = __expf(s * T_INV);
    out[(long long)b * NC] = e;
    atomicAdd(&g_rowsum[b], e);
}

// ---------------- K2: persistent split-bf16 GEMM + hybrid exp ----------------
// SMEM 192KB: A hi/lo (64KB resident) + two B buffers (64KB each, hi/lo).
// Each array: 128 rows x 256B, 16B chunks XOR-swizzled by (row&7).
extern __shared__ char smem_g[];

__device__ __forceinline__ void issueB(int bn, int buf, uint32_t sbase, int t) {
    const uint4* hi = reinterpret_cast<const uint4*>(g_mem_hi) + (size_t)bn * 2048;
    const uint4* lo = reinterpret_cast<const uint4*>(g_mem_lo) + (size_t)bn * 2048;
    uint32_t base = sbase + 65536 + (uint32_t)buf * 65536;
    #pragma unroll
    for (int it = 0; it < 16; it++) {
        int fid = it * 256 + t;
        int arr = fid >> 11;
        int within = fid & 2047;
        int row = within >> 4, ch = within & 15;
        const uint4* src = (arr ? lo : hi) + row * 16 + ch;
        uint32_t dst = base + (uint32_t)(arr * 32768 + row * 256 + ((ch ^ (row & 7)) << 4));
        CP_ASYNC16(dst, src);
    }
}
__device__ __forceinline__ void stageA(int bm, int t) {
    const uint4* hi = reinterpret_cast<const uint4*>(g_q_hi) + (size_t)bm * 2048;
    const uint4* lo = reinterpret_cast<const uint4*>(g_q_lo) + (size_t)bm * 2048;
    #pragma unroll
    for (int it = 0; it < 16; it++) {
        int fid = it * 256 + t;
        int arr = fid >> 11;
        int within = fid & 2047;
        int row = within >> 4, ch = within & 15;
        uint4 v = (arr ? lo : hi)[row * 16 + ch];
        *reinterpret_cast<uint4*>(smem_g + arr * 32768 + row * 256 + ((ch ^ (row & 7)) << 4)) = v;
    }
}

__global__ __launch_bounds__(256, 1)
void gemm_k(float* __restrict__ out) {
    uint32_t sbase = smem_u32(smem_g);
    int t = threadIdx.x;
    int w = t >> 5, lane = t & 31;
    int wm = w >> 1, wn = w & 1;
    int a_r = (lane & 7) + ((lane >> 3) & 1) * 8;
    int a_c = (lane >> 4) & 1;
    int b_r = (lane & 7) + ((lane >> 4) & 1) * 8;
    int b_c = (lane >> 3) & 1;
    int grp = lane >> 2, tid4 = lane & 3;

    float rs[2][2] = {{0.f, 0.f}, {0.f, 0.f}};

    int tile0 = blockIdx.x;
    int curBm = tile0 >> 10;

    issueB(tile0 & 1023, 0, sbase, t);
    CP_COMMIT();
    stageA(curBm, t);

    const uint32_t AH = sbase, AL = sbase + 32768;

    int idx = 0;
    for (int tile = tile0; tile < NTILES; tile += GRID_GEMM, idx++) {
        int nxt = tile + GRID_GEMM;
        if (nxt < NTILES) {
            issueB(nxt & 1023, (idx + 1) & 1, sbase, t);
            CP_COMMIT();
            CP_WAIT1();
        } else {
            CP_WAIT0();
        }
        __syncthreads();

        int bm = tile >> 10;
        if (bm != curBm) {
            #pragma unroll
            for (int mt = 0; mt < 2; mt++) {
                int r0 = curBm * 128 + wm * 32 + mt * 16 + grp;
                atomicAdd(&g_rowsum[r0], rs[mt][0]);
                atomicAdd(&g_rowsum[r0 + 8], rs[mt][1]);
                rs[mt][0] = rs[mt][1] = 0.f;
            }
            curBm = bm;
            stageA(bm, t);
            __syncthreads();
        }

        uint32_t BH = sbase + 65536 + (uint32_t)(idx & 1) * 65536;
        uint32_t BL = BH + 32768;
        int bn = tile & 1023;

        float acc[2][8][4];
        #pragma unroll
        for (int mt = 0; mt < 2; mt++)
            #pragma unroll
            for (int nt = 0; nt < 8; nt++)
                #pragma unroll
                for (int r = 0; r < 4; r++) acc[mt][nt][r] = 0.f;

        #pragma unroll
        for (int ks = 0; ks < 8; ks++) {
            uint32_t ah[2][4], al[2][4];
            #pragma unroll
            for (int mt = 0; mt < 2; mt++) {
                int r = wm * 32 + mt * 16 + a_r;
                int ch = ks * 2 + a_c;
                uint32_t off = (uint32_t)(r * 256 + ((ch ^ (r & 7)) << 4));
                ldm_x4(ah[mt], AH + off);
                ldm_x4(al[mt], AL + off);
            }
            #pragma unroll
            for (int np = 0; np < 4; np++) {
                int n = wn * 64 + np * 16 + b_r;
                int ch = ks * 2 + b_c;
                uint32_t off = (uint32_t)(n * 256 + ((ch ^ (n & 7)) << 4));
                uint32_t bh[4], bl[4];
                ldm_x4(bh, BH + off);
                ldm_x4(bl, BL + off);
                #pragma unroll
                for (int sub = 0; sub < 2; sub++) {
                    int nt = np * 2 + sub;
                    #pragma unroll
                    for (int mt = 0; mt < 2; mt++) {
                        mma_bf16(acc[mt][nt], ah[mt], bh[2 * sub], bh[2 * sub + 1]);
                        mma_bf16(acc[mt][nt], ah[mt], bl[2 * sub], bl[2 * sub + 1]);
                        mma_bf16(acc[mt][nt], al[mt], bh[2 * sub], bh[2 * sub + 1]);
                    }
                }
            }
        }

        // ---- epilogue: hybrid exp (poly on FMA pipe / MUFU), store, rowsum ----
        #pragma unroll
        for (int mt = 0; mt < 2; mt++) {
            int r0l = wm * 32 + mt * 16 + grp;
            long long m0 = (long long)(bm * 128 + r0l);
            long long base0 = m0 * NC + 1 + (long long)bn * 128 + wn * 64;
            long long base1 = base0 + 8LL * NC;
            float s0 = 0.f, s1 = 0.f;
            #pragma unroll
            for (int nt = 0; nt < 8; nt++) {
                int cb = nt * 8 + tid4 * 2;
                float e00, e01, e10, e11;
                if (nt < 4) {
                    float2 p0 = exp_pair(acc[mt][nt][0], acc[mt][nt][1]);
                    float2 p1 = exp_pair(acc[mt][nt][2], acc[mt][nt][3]);
                    e00 = p0.x; e01 = p0.y; e10 = p1.x; e11 = p1.y;
                } else {
                    e00 = __expf(acc[mt][nt][0] * T_INV);
                    e01 = __expf(acc[mt][nt][1] * T_INV);
                    e10 = __expf(acc[mt][nt][2] * T_INV);
                    e11 = __expf(acc[mt][nt][3] * T_INV);
                }
                out[base0 + cb]     = e00;
                out[base0 + cb + 1] = e01;
                out[base1 + cb]     = e10;
                out[base1 + cb + 1] = e11;
                s0 += e00 + e01;
                s1 += e10 + e11;
            }
            rs[mt][0] += s0; rs[mt][1] += s1;
        }
        __syncthreads();
    }

    #pragma unroll
    for (int mt = 0; mt < 2; mt++) {
        int r0 = curBm * 128 + wm * 32 + mt * 16 + grp;
        atomicAdd(&g_rowsum[r0], rs[mt][0]);
        atomicAdd(&g_rowsum[r0 + 8], rs[mt][1]);
    }
}

// ---------------- K3: finalize Z, invZ, probs ----------------
__global__ void finalize_k(float* __restrict__ out) {
    __shared__ float sZ[256], sP[256];
    int t = threadIdx.x;
    float rsv = g_rowsum[t];
    float e0 = out[(long long)t * NC];
    sZ[t] = rsv;
    sP[t] = e0 / rsv;
    __syncthreads();
    for (int s = 128; s > 0; s >>= 1) {
        if (t < s) { sZ[t] += sZ[t + s]; sP[t] += sP[t + s]; }
        __syncthreads();
    }
    if (t == 0) {
        float Z = sZ[0] / ((float)BSZ * (float)NC) * OUTPUT_SIZE;
        g_invZ = 1.f / Z;
        out[PROBS_OFF] = sP[0] * (1.0f / 256.0f);
    }
}

// ---------------- K4: fused scale + memory-bank update ----------------
__global__ void scalemem_k(const float* __restrict__ kk, const float* __restrict__ mem,
                           float* __restrict__ out) {
    const long long G1 = OUT_ELEMS / 4;          // 8,388,672 vec4 scale groups
    const long long G2 = (long long)QK * DIM;    // 16,777,216 memup elements
    float inv = g_invZ;
    long long stride = (long long)gridDim.x * blockDim.x;
    for (long long i = (long long)blockIdx.x * blockDim.x + threadIdx.x;
         i < G1 + G2; i += stride) {
        if (i < G1) {
            float4* o4 = reinterpret_cast<float4*>(out);
            float4 v = o4[i];
            v.x *= inv; v.y *= inv; v.z *= inv; v.w *= inv;
            o4[i] = v;
        } else {
            long long p = i - G1;
            int r = (int)(p >> 7), d = (int)(p & 127);
            float v;
            if (r < 64) {
                v = 0.25f * (kk[r * DIM + d] + kk[(r + 64) * DIM + d] +
                             kk[(r + 128) * DIM + d] + kk[(r + 192) * DIM + d]);
            } else {
                v = mem[p];
            }
            out[MEM_OFF + p] = v;
        }
    }
}

// ---------------- launch ----------------
extern "C" void kernel_launch(void* const* d_in, const int* in_sizes, int n_in,
                              void* d_out, int out_size) {
    const float* q   = (const float*)d_in[0];
    const float* k   = (const float*)d_in[1];
    const float* mem = (const float*)d_in[2];
    float* out = (float*)d_out;

    cudaFuncSetAttribute(gemm_k, cudaFuncAttributeMaxDynamicSharedMemorySize, 196608);

    split_k<<<2048, 256>>>(q, mem);
    zero_k<<<1, 256>>>();
    lpos_k<<<1, 256>>>(q, k, out);
    gemm_k<<<GRID_GEMM, 256, 196608>>>(out);
    finalize_k<<<1, 256>>>(out);
    scalemem_k<<<8192, 256>>>(k, mem, out);
}

// round 9
// speedup vs baseline: 2.0651x; 1.0016x over previous
#include <cuda_runtime.h>
#include <cuda_bf16.h>
#include <cstdint>

// ---------------- problem constants ----------------
#define BSZ   256
#define DIM   128
#define QK    131072
#define NC    131073
#define OUT_ELEMS (BSZ * (long long)NC)      // 33,554,688
#define PROBS_OFF OUT_ELEMS
#define MEM_OFF   (OUT_ELEMS + 1)
#define T_INV 14.2857142857142857f
#define OUTPUT_SIZE 1000000.0f
#define GRID_GEMM 148
#define NTILES    2048
#define GTHREADS  512

// ---------------- device scratch ----------------
__device__ float g_rowsum[BSZ];
__device__ float g_invZ;
__device__ __nv_bfloat16 g_mem_hi[QK * DIM];   // 32 MB
__device__ __nv_bfloat16 g_mem_lo[QK * DIM];   // 32 MB
__device__ __nv_bfloat16 g_q_hi[BSZ * DIM];
__device__ __nv_bfloat16 g_q_lo[BSZ * DIM];

// ---------------- helpers ----------------
__device__ __forceinline__ uint32_t smem_u32(const void* p) {
    uint32_t a;
    asm("{ .reg .u64 t; cvta.to.shared.u64 t, %1; cvt.u32.u64 %0, t; }" : "=r"(a) : "l"(p));
    return a;
}
__device__ __forceinline__ void ldm_x4(uint32_t* r, uint32_t addr) {
    asm volatile("ldmatrix.sync.aligned.m8n8.x4.shared.b16 {%0,%1,%2,%3}, [%4];"
                 : "=r"(r[0]), "=r"(r[1]), "=r"(r[2]), "=r"(r[3]) : "r"(addr));
}
__device__ __forceinline__ void mma_bf16(float* d, const uint32_t* a, uint32_t b0, uint32_t b1) {
    asm volatile(
        "mma.sync.aligned.m16n8k16.row.col.f32.bf16.bf16.f32 "
        "{%0,%1,%2,%3}, {%4,%5,%6,%7}, {%8,%9}, {%0,%1,%2,%3};"
        : "+f"(d[0]), "+f"(d[1]), "+f"(d[2]), "+f"(d[3])
        : "r"(a[0]), "r"(a[1]), "r"(a[2]), "r"(a[3]), "r"(b0), "r"(b1));
}
#define CP_ASYNC16(dst, src) \
    asm volatile("{ .reg .u64 g; cvta.to.global.u64 g, %1; cp.async.cg.shared.global [%0], [g], 16; }" \
                 :: "r"(dst), "l"(src) : "memory")
#define CP_COMMIT() asm volatile("cp.async.commit_group;" ::: "memory")
#define CP_WAIT1()  asm volatile("cp.async.wait_group 1;" ::: "memory")
#define CP_WAIT0()  asm volatile("cp.async.wait_group 0;" ::: "memory")

// ---- packed f32x2 ----
__device__ __forceinline__ unsigned long long dup2(float x) {
    unsigned long long r; unsigned int u = __float_as_uint(x);
    asm("mov.b64 %0, {%1, %1};" : "=l"(r) : "r"(u));
    return r;
}
__device__ __forceinline__ unsigned long long fma2(unsigned long long a,
                                                   unsigned long long b,
                                                   unsigned long long c) {
    unsigned long long d;
    asm("fma.rn.f32x2 %0, %1, %2, %3;" : "=l"(d) : "l"(a), "l"(b), "l"(c));
    return d;
}
__device__ __forceinline__ unsigned long long add2(unsigned long long a, unsigned long long b) {
    unsigned long long d;
    asm("add.rn.f32x2 %0, %1, %2;" : "=l"(d) : "l"(a), "l"(b));
    return d;
}
__device__ __forceinline__ unsigned long long mul2(unsigned long long a, unsigned long long b) {
    unsigned long long d;
    asm("mul.rn.f32x2 %0, %1, %2;" : "=l"(d) : "l"(a), "l"(b));
    return d;
}

// exp(s/T) for a pair, via packed exp2 on the FMA pipe.
__device__ __forceinline__ float2 exp_pair(float a, float b) {
    unsigned long long sp;
    asm("mov.b64 %0, {%1,%2};" : "=l"(sp) : "f"(a), "f"(b));
    const unsigned long long S  = dup2(20.60992908f);       // (1/0.07)*log2(e)
    const unsigned long long MG = dup2(12582912.0f);        // 1.5*2^23
    unsigned long long t  = fma2(sp, S, MG);
    unsigned long long nf = add2(t, dup2(-12582912.0f));    // n as float
    unsigned long long f  = fma2(sp, S, nf ^ 0x8000000080000000ULL);  // y - n
    unsigned long long r  = fma2(f, dup2(0.00133335581464f), dup2(0.00961812910763f));
    r = fma2(r, f, dup2(0.0555041086648f));
    r = fma2(r, f, dup2(0.240226506959f));
    r = fma2(r, f, dup2(0.69314718056f));
    r = fma2(r, f, dup2(1.0f));
    uint32_t t0, t1;
    asm("mov.b64 {%0,%1}, %2;" : "=r"(t0), "=r"(t1) : "l"(t));
    uint32_t sb0 = (t0 << 23) + 0x3F800000u;
    uint32_t sb1 = (t1 << 23) + 0x3F800000u;
    unsigned long long sc;
    asm("mov.b64 %0, {%1,%2};" : "=l"(sc) : "r"(sb0), "r"(sb1));
    unsigned long long res = mul2(r, sc);
    float x, y;
    asm("mov.b64 {%0,%1}, %2;" : "=f"(x), "=f"(y) : "l"(res));
    return make_float2(x, y);
}

// ---------------- split ----------------
__device__ __forceinline__ void split1(float x, __nv_bfloat16& h, __nv_bfloat16& l) {
    h = __float2bfloat16(x);
    l = __float2bfloat16(x - __bfloat162float(h));
}
__global__ void split_k(const float* __restrict__ q, const float* __restrict__ mem) {
    const long long QN4 = (BSZ * DIM) / 4;
    const long long MN4 = ((long long)QK * DIM) / 4;
    long long i = (long long)blockIdx.x * blockDim.x + threadIdx.x;
    long long stride = (long long)gridDim.x * blockDim.x;
    for (long long p = i; p < QN4 + MN4; p += stride) {
        float4 v;
        uint2* dh; uint2* dl; long long idx;
        if (p < QN4) {
            v = reinterpret_cast<const float4*>(q)[p];
            dh = reinterpret_cast<uint2*>(g_q_hi); dl = reinterpret_cast<uint2*>(g_q_lo);
            idx = p;
        } else {
            v = reinterpret_cast<const float4*>(mem)[p - QN4];
            dh = reinterpret_cast<uint2*>(g_mem_hi); dl = reinterpret_cast<uint2*>(g_mem_lo);
            idx = p - QN4;
        }
        __nv_bfloat16 h0, l0, h1, l1, h2, l2, h3, l3;
        split1(v.x, h0, l0); split1(v.y, h1, l1);
        split1(v.z, h2, l2); split1(v.w, h3, l3);
        __nv_bfloat162 hp0(h0, h1), hp1(h2, h3), lp0(l0, l1), lp1(l2, l3);
        uint2 uh, ul;
        uh.x = *reinterpret_cast<uint32_t*>(&hp0); uh.y = *reinterpret_cast<uint32_t*>(&hp1);
        ul.x = *reinterpret_cast<uint32_t*>(&lp0); ul.y = *reinterpret_cast<uint32_t*>(&lp1);
        dh[idx] = uh; dl[idx] = ul;
    }
}

// ---------------- zero + l_pos ----------------
__global__ void zero_k() {
    if (threadIdx.x < BSZ) g_rowsum[threadIdx.x] = 0.f;
}
__global__ void lpos_k(const float* __restrict__ q, const float* __restrict__ k,
                       float* __restrict__ out) {
    int b = threadIdx.x;
    int vid = b & 63;
    const float* qb = q + b * DIM;
    float s = 0.f;
    #pragma unroll
    for (int c = 0; c < 4; c++) {
        int r = vid + c * 64;
        if (r == b) continue;
        const float* kr = k + r * DIM;
        float d = 0.f;
        #pragma unroll
        for (int j = 0; j < DIM; j++) d += kr[j] * qb[j];
        s += d;
    }
    s *= (1.0f / 3.0f);
    float e = __expf(s * T_INV);
    out[(long long)b * NC] = e;
    atomicAdd(&g_rowsum[b], e);
}

// ---------------- persistent GEMM (512 thr, 16 warps) + memup tail -------
// SMEM 192KB: A hi/lo (64KB resident) + two B buffers (64KB each).
extern __shared__ char smem_g[];

__device__ __forceinline__ void issueB(int bn, int buf, uint32_t sbase, int t) {
    const uint4* hi = reinterpret_cast<const uint4*>(g_mem_hi) + (size_t)bn * 2048;
    const uint4* lo = reinterpret_cast<const uint4*>(g_mem_lo) + (size_t)bn * 2048;
    uint32_t base = sbase + 65536 + (uint32_t)buf * 65536;
    #pragma unroll
    for (int it = 0; it < 8; it++) {
        int fid = it * GTHREADS + t;
        int arr = fid >> 11;
        int within = fid & 2047;
        int row = within >> 4, ch = within & 15;
        const uint4* src = (arr ? lo : hi) + row * 16 + ch;
        uint32_t dst = base + (uint32_t)(arr * 32768 + row * 256 + ((ch ^ (row & 7)) << 4));
        CP_ASYNC16(dst, src);
    }
}
__device__ __forceinline__ void stageA(int bm, int t) {
    const uint4* hi = reinterpret_cast<const uint4*>(g_q_hi) + (size_t)bm * 2048;
    const uint4* lo = reinterpret_cast<const uint4*>(g_q_lo) + (size_t)bm * 2048;
    #pragma unroll
    for (int it = 0; it < 8; it++) {
        int fid = it * GTHREADS + t;
        int arr = fid >> 11;
        int within = fid & 2047;
        int row = within >> 4, ch = within & 15;
        uint4 v = (arr ? lo : hi)[row * 16 + ch];
        *reinterpret_cast<uint4*>(smem_g + arr * 32768 + row * 256 + ((ch ^ (row & 7)) << 4)) = v;
    }
}

__global__ __launch_bounds__(GTHREADS, 1)
void gemm_k(float* __restrict__ out, const float* __restrict__ kk,
            const float* __restrict__ memp) {
    uint32_t sbase = smem_u32(smem_g);
    int t = threadIdx.x;
    int w = t >> 5, lane = t & 31;
    int wm = w >> 2, wn = w & 3;          // warp tile: rows wm*32, cols wn*32
    int a_r = (lane & 7) + ((lane >> 3) & 1) * 8;
    int a_c = (lane >> 4) & 1;
    int b_r = (lane & 7) + ((lane >> 4) & 1) * 8;
    int b_c = (lane >> 3) & 1;
    int grp = lane >> 2, tid4 = lane & 3;

    float rs[2][2] = {{0.f, 0.f}, {0.f, 0.f}};

    int tile0 = blockIdx.x;
    int curBm = tile0 >> 10;

    issueB(tile0 & 1023, 0, sbase, t);
    CP_COMMIT();
    stageA(curBm, t);

    const uint32_t AH = sbase, AL = sbase + 32768;

    int idx = 0;
    for (int tile = tile0; tile < NTILES; tile += GRID_GEMM, idx++) {
        int nxt = tile + GRID_GEMM;
        if (nxt < NTILES) {
            issueB(nxt & 1023, (idx + 1) & 1, sbase, t);
            CP_COMMIT();
            CP_WAIT1();
        } else {
            CP_WAIT0();
        }
        __syncthreads();

        int bm = tile >> 10;
        if (bm != curBm) {
            #pragma unroll
            for (int mt = 0; mt < 2; mt++) {
                int r0 = curBm * 128 + wm * 32 + mt * 16 + grp;
                atomicAdd(&g_rowsum[r0], rs[mt][0]);
                atomicAdd(&g_rowsum[r0 + 8], rs[mt][1]);
                rs[mt][0] = rs[mt][1] = 0.f;
            }
            curBm = bm;
            stageA(bm, t);
            __syncthreads();
        }

        uint32_t BH = sbase + 65536 + (uint32_t)(idx & 1) * 65536;
        uint32_t BL = BH + 32768;
        int bn = tile & 1023;

        float acc[2][4][4];
        #pragma unroll
        for (int mt = 0; mt < 2; mt++)
            #pragma unroll
            for (int nt = 0; nt < 4; nt++)
                #pragma unroll
                for (int r = 0; r < 4; r++) acc[mt][nt][r] = 0.f;

        #pragma unroll
        for (int ks = 0; ks < 8; ks++) {
            uint32_t ah[2][4], al[2][4];
            #pragma unroll
            for (int mt = 0; mt < 2; mt++) {
                int r = wm * 32 + mt * 16 + a_r;
                int ch = ks * 2 + a_c;
                uint32_t off = (uint32_t)(r * 256 + ((ch ^ (r & 7)) << 4));
                ldm_x4(ah[mt], AH + off);
                ldm_x4(al[mt], AL + off);
            }
            #pragma unroll
            for (int np = 0; np < 2; np++) {
                int n = wn * 32 + np * 16 + b_r;
                int ch = ks * 2 + b_c;
                uint32_t off = (uint32_t)(n * 256 + ((ch ^ (n & 7)) << 4));
                uint32_t bh[4], bl[4];
                ldm_x4(bh, BH + off);
                ldm_x4(bl, BL + off);
                #pragma unroll
                for (int sub = 0; sub < 2; sub++) {
                    int nt = np * 2 + sub;
                    #pragma unroll
                    for (int mt = 0; mt < 2; mt++) {
                        mma_bf16(acc[mt][nt], ah[mt], bh[2 * sub], bh[2 * sub + 1]);
                        mma_bf16(acc[mt][nt], ah[mt], bl[2 * sub], bl[2 * sub + 1]);
                        mma_bf16(acc[mt][nt], al[mt], bh[2 * sub], bh[2 * sub + 1]);
                    }
                }
            }
        }

        // ---- epilogue: hybrid exp, store, rowsum ----
        #pragma unroll
        for (int mt = 0; mt < 2; mt++) {
            int r0l = wm * 32 + mt * 16 + grp;
            long long m0 = (long long)(bm * 128 + r0l);
            long long base0 = m0 * NC + 1 + (long long)bn * 128 + wn * 32;
            long long base1 = base0 + 8LL * NC;
            float s0 = 0.f, s1 = 0.f;
            #pragma unroll
            for (int nt = 0; nt < 4; nt++) {
                int cb = nt * 8 + tid4 * 2;
                float e00, e01, e10, e11;
                if (nt < 2) {
                    float2 p0 = exp_pair(acc[mt][nt][0], acc[mt][nt][1]);
                    float2 p1 = exp_pair(acc[mt][nt][2], acc[mt][nt][3]);
                    e00 = p0.x; e01 = p0.y; e10 = p1.x; e11 = p1.y;
                } else {
                    e00 = __expf(acc[mt][nt][0] * T_INV);
                    e01 = __expf(acc[mt][nt][1] * T_INV);
                    e10 = __expf(acc[mt][nt][2] * T_INV);
                    e11 = __expf(acc[mt][nt][3] * T_INV);
                }
                out[base0 + cb]     = e00;
                out[base0 + cb + 1] = e01;
                out[base1 + cb]     = e10;
                out[base1 + cb + 1] = e11;
                s0 += e00 + e01;
                s1 += e10 + e11;
            }
            rs[mt][0] += s0; rs[mt][1] += s1;
        }
        __syncthreads();
    }

    #pragma unroll
    for (int mt = 0; mt < 2; mt++) {
        int r0 = curBm * 128 + wm * 32 + mt * 16 + grp;
        atomicAdd(&g_rowsum[r0], rs[mt][0]);
        atomicAdd(&g_rowsum[r0 + 8], rs[mt][1]);
    }

    // ---- memup tail (independent of Z): memory-bank scatter-copy ----
    {
        const long long N = (long long)QK * DIM;
        long long stride = (long long)GRID_GEMM * GTHREADS;
        for (long long p = (long long)blockIdx.x * GTHREADS + t; p < N; p += stride) {
            int r = (int)(p >> 7), d = (int)(p & 127);
            float v;
            if (r < 64) {
                v = 0.25f * (kk[r * DIM + d] + kk[(r + 64) * DIM + d] +
                             kk[(r + 128) * DIM + d] + kk[(r + 192) * DIM + d]);
            } else {
                v = memp[p];
            }
            out[MEM_OFF + p] = v;
        }
    }
}

// ---------------- finalize ----------------
__global__ void finalize_k(float* __restrict__ out) {
    __shared__ float sZ[256], sP[256];
    int t = threadIdx.x;
    float rsv = g_rowsum[t];
    float e0 = out[(long long)t * NC];
    sZ[t] = rsv;
    sP[t] = e0 / rsv;
    __syncthreads();
    for (int s = 128; s > 0; s >>= 1) {
        if (t < s) { sZ[t] += sZ[t + s]; sP[t] += sP[t + s]; }
        __syncthreads();
    }
    if (t == 0) {
        float Z = sZ[0] / ((float)BSZ * (float)NC) * OUTPUT_SIZE;
        g_invZ = 1.f / Z;
        out[PROBS_OFF] = sP[0] * (1.0f / 256.0f);
    }
}

// ---------------- scale out by 1/Z ----------------
__global__ void scale_k(float* __restrict__ out) {
    float inv = g_invZ;
    long long i = (long long)blockIdx.x * blockDim.x + threadIdx.x;
    long long stride = (long long)gridDim.x * blockDim.x;
    float4* o4 = reinterpret_cast<float4*>(out);
    const long long n4 = OUT_ELEMS / 4;
    for (long long p = i; p < n4; p += stride) {
        float4 v = o4[p];
        v.x *= inv; v.y *= inv; v.z *= inv; v.w *= inv;
        o4[p] = v;
    }
}

// ---------------- launch ----------------
extern "C" void kernel_launch(void* const* d_in, const int* in_sizes, int n_in,
                              void* d_out, int out_size) {
    const float* q   = (const float*)d_in[0];
    const float* k   = (const float*)d_in[1];
    const float* mem = (const float*)d_in[2];
    float* out = (float*)d_out;

    cudaFuncSetAttribute(gemm_k, cudaFuncAttributeMaxDynamicSharedMemorySize, 196608);

    split_k<<<2048, 256>>>(q, mem);
    zero_k<<<1, 256>>>();
    lpos_k<<<1, 256>>>(q, k, out);
    gemm_k<<<GRID_GEMM, GTHREADS, 196608>>>(out, k, mem);
    finalize_k<<<1, 256>>>(out);
    scale_k<<<4096, 256>>>(out);
}